// round 2
// baseline (speedup 1.0000x reference)
#include <cuda_runtime.h>
#include <cuda_bf16.h>

// Problem: per-species linear (X[n,64] . W[species[n],64,1]) + segment_sum over
// sorted structural_indices -> out[n_structures, 1].
// HBM-bound: ~528 MB streamed. Strategy: 16 lanes per atom (float4 each),
// shfl reduce, sorted-run aggregation, rare atomicAdd flushes.

#define WARPS_PER_BLOCK 8
#define THREADS_PER_BLOCK (WARPS_PER_BLOCK * 32)
#define N_SPECIES 8
#define D_FEAT 64
#define D_VEC4 (D_FEAT / 4)   // 16 float4 per row

__global__ __launch_bounds__(THREADS_PER_BLOCK)
void atomistic_kernel(const float4* __restrict__ X4,
                      const float*  __restrict__ W,
                      const int*    __restrict__ species,
                      const int*    __restrict__ struct_idx,
                      float*        __restrict__ out,
                      int n_atoms,
                      int atoms_per_warp)
{
    // Stage W (8 x 64 fp32 = 2 KB) into shared as float4
    __shared__ float4 Wsh[N_SPECIES * D_VEC4];
    for (int i = threadIdx.x; i < N_SPECIES * D_VEC4; i += blockDim.x)
        Wsh[i] = reinterpret_cast<const float4*>(W)[i];
    __syncthreads();

    const int warp = blockIdx.x * WARPS_PER_BLOCK + (threadIdx.x >> 5);
    const int lane = threadIdx.x & 31;
    const int half = lane >> 4;    // which atom of the pair this lane works on
    const int sub  = lane & 15;    // float4 index within the 64-float row

    long long start = (long long)warp * atoms_per_warp;
    long long end   = start + atoms_per_warp;
    if (end > n_atoms) end = (long long)n_atoms;
    if (start >= end) return;      // uniform per warp -> whole warp exits

    // Running segment accumulator per leader lane (sub == 0 -> lanes 0 and 16).
    int   cur_key = -1;
    float cur_sum = 0.0f;

    for (long long base = start; base < end; base += 2) {
        const long long a = base + half;
        const bool active = (a < end);

        float d = 0.0f;
        int key = -1;
        if (active) {
            const int s = species[a];
            const float4 x = X4[a * D_VEC4 + sub];
            const float4 w = Wsh[s * D_VEC4 + sub];
            d = x.x * w.x + x.y * w.y + x.z * w.z + x.w * w.w;
            if (sub == 0)
                key = struct_idx[a];
        }

        // Butterfly reduce within each 16-lane half (all 32 lanes participate).
        d += __shfl_xor_sync(0xffffffffu, d, 8);
        d += __shfl_xor_sync(0xffffffffu, d, 4);
        d += __shfl_xor_sync(0xffffffffu, d, 2);
        d += __shfl_xor_sync(0xffffffffu, d, 1);

        if (sub == 0 && active) {
            if (key == cur_key) {
                cur_sum += d;
            } else {
                if (cur_key >= 0) atomicAdd(out + cur_key, cur_sum);
                cur_key = key;
                cur_sum = d;
            }
        }
    }

    if (sub == 0 && cur_key >= 0)
        atomicAdd(out + cur_key, cur_sum);
}

extern "C" void kernel_launch(void* const* d_in, const int* in_sizes, int n_in,
                              void* d_out, int out_size)
{
    // Input order (setup_inputs): X, W, central_species, structural_indices, n_structures
    const float* X  = (const float*)d_in[0];
    const float* W  = (const float*)d_in[1];
    const int*   sp = (const int*)  d_in[2];
    const int*   si = (const int*)  d_in[3];
    float* out = (float*)d_out;

    const int n_atoms = in_sizes[2];   // species array length == N_ATOMS

    // Output is poisoned; zero it (graph-capturable memset node).
    cudaMemsetAsync(d_out, 0, (size_t)out_size * sizeof(float), 0);

    const int blocks = 592;  // 4 CTAs/SM * 148 SMs
    const int total_warps = blocks * WARPS_PER_BLOCK;
    const int atoms_per_warp = (n_atoms + total_warps - 1) / total_warps;

    atomistic_kernel<<<blocks, THREADS_PER_BLOCK>>>(
        (const float4*)X, W, sp, si, out, n_atoms, atoms_per_warp);
}

// round 3
// speedup vs baseline: 1.6018x; 1.6018x over previous
#include <cuda_runtime.h>
#include <cuda_bf16.h>

// Per-species linear (X[n,64] . W[species[n],64,1]) + segment_sum over sorted
// structural_indices -> out[n_structures].
// HBM-bound (~528 MB streamed). R2 change: per-lane partial accumulators held
// across an entire sorted segment; the 16-lane shuffle reduction fires only at
// segment boundaries (~1/100 atoms), removing the shuffle chain from the hot
// loop. 8 CTAs/SM for full occupancy; __ldcs streaming loads for X.

#define WARPS_PER_BLOCK 8
#define THREADS_PER_BLOCK (WARPS_PER_BLOCK * 32)
#define N_SPECIES 8
#define D_FEAT 64
#define D_VEC4 (D_FEAT / 4)   // 16 float4 per row

__global__ __launch_bounds__(THREADS_PER_BLOCK)
void atomistic_kernel(const float4* __restrict__ X4,
                      const float*  __restrict__ W,
                      const int*    __restrict__ species,
                      const int*    __restrict__ struct_idx,
                      float*        __restrict__ out,
                      int n_atoms,
                      int atoms_per_warp)
{
    // Stage W (8 x 64 fp32 = 2 KB) into shared as float4
    __shared__ float4 Wsh[N_SPECIES * D_VEC4];
    for (int i = threadIdx.x; i < N_SPECIES * D_VEC4; i += blockDim.x)
        Wsh[i] = reinterpret_cast<const float4*>(W)[i];
    __syncthreads();

    const int warp = blockIdx.x * WARPS_PER_BLOCK + (threadIdx.x >> 5);
    const int lane = threadIdx.x & 31;
    const int half = lane >> 4;                 // atom slot within the pair
    const int sub  = lane & 15;                 // float4 index within the row
    const unsigned halfmask = 0xFFFFu << (half * 16);

    long long start = (long long)warp * atoms_per_warp;
    long long end   = start + atoms_per_warp;
    if (end > n_atoms) end = (long long)n_atoms;
    if (start >= end) return;                   // uniform per warp

    // Per-lane partial sum for the current segment (keys are sorted, so each
    // half-warp sees monotone keys; all 16 lanes of a half share the key).
    int   cur_key = -1;
    float acc     = 0.0f;

    #pragma unroll 2
    for (long long base = start; base < end; base += 2) {
        const long long a = base + half;
        if (a < end) {                          // uniform within each half
            const int key = struct_idx[a];      // 4B broadcast load
            if (key != cur_key) {
                // Segment boundary: reduce the previous segment across the
                // 16 lanes of this half and flush. Rare (~1% of iterations).
                float s = acc;
                s += __shfl_xor_sync(halfmask, s, 8);
                s += __shfl_xor_sync(halfmask, s, 4);
                s += __shfl_xor_sync(halfmask, s, 2);
                s += __shfl_xor_sync(halfmask, s, 1);
                if (sub == 0 && cur_key >= 0)
                    atomicAdd(out + cur_key, s);
                cur_key = key;
                acc = 0.0f;
            }
            const int s = species[a];           // 4B broadcast load
            const float4 x = __ldcs(&X4[a * D_VEC4 + sub]);  // streaming
            const float4 w = Wsh[s * D_VEC4 + sub];
            acc = fmaf(x.x, w.x, acc);
            acc = fmaf(x.y, w.y, acc);
            acc = fmaf(x.z, w.z, acc);
            acc = fmaf(x.w, w.w, acc);
        }
    }

    // Final flush (all 32 lanes reach here; reduce each half).
    float s = acc;
    s += __shfl_xor_sync(0xFFFFFFFFu, s, 8);
    s += __shfl_xor_sync(0xFFFFFFFFu, s, 4);
    s += __shfl_xor_sync(0xFFFFFFFFu, s, 2);
    s += __shfl_xor_sync(0xFFFFFFFFu, s, 1);
    if (sub == 0 && cur_key >= 0)
        atomicAdd(out + cur_key, s);
}

extern "C" void kernel_launch(void* const* d_in, const int* in_sizes, int n_in,
                              void* d_out, int out_size)
{
    // Input order: X, W, central_species, structural_indices, n_structures
    const float* X  = (const float*)d_in[0];
    const float* W  = (const float*)d_in[1];
    const int*   sp = (const int*)  d_in[2];
    const int*   si = (const int*)  d_in[3];
    float* out = (float*)d_out;

    const int n_atoms = in_sizes[2];

    // Output is poisoned; zero it (graph-capturable memset node).
    cudaMemsetAsync(d_out, 0, (size_t)out_size * sizeof(float), 0);

    const int blocks = 1184;  // 8 CTAs/SM * 148 SMs -> 64 warps/SM
    const int total_warps = blocks * WARPS_PER_BLOCK;
    const int atoms_per_warp = (n_atoms + total_warps - 1) / total_warps;

    atomistic_kernel<<<blocks, THREADS_PER_BLOCK>>>(
        (const float4*)X, W, sp, si, out, n_atoms, atoms_per_warp);
}

// round 4
// speedup vs baseline: 1.8040x; 1.1262x over previous
#include <cuda_runtime.h>
#include <cuda_bf16.h>

// Per-species linear (X[n,64] . W[species[n],64,1]) + segment_sum over sorted
// structural_indices -> out[n_structures].
// R3: 8-atom warp batches (half-warp owns 4 contiguous atoms), int4 key/species
// loads, 4 front-batched __ldcs float4 X loads per lane (MLP), sorted-run fast
// path (whole batch in one segment -> straight FMAs), pointer-increment
// addressing. Shuffle reduction + atomicAdd only at segment boundaries.

#define WARPS_PER_BLOCK 8
#define THREADS_PER_BLOCK (WARPS_PER_BLOCK * 32)
#define N_SPECIES 8
#define D_VEC4 16   // 64 floats / 4

__global__ __launch_bounds__(THREADS_PER_BLOCK)
void atomistic_kernel(const float4* __restrict__ X4,
                      const float*  __restrict__ W,
                      const int*    __restrict__ species,
                      const int*    __restrict__ struct_idx,
                      float*        __restrict__ out,
                      int n_atoms,
                      int atoms_per_warp)   // multiple of 8
{
    __shared__ float4 Wsh[N_SPECIES * D_VEC4];
    for (int i = threadIdx.x; i < N_SPECIES * D_VEC4; i += blockDim.x)
        Wsh[i] = reinterpret_cast<const float4*>(W)[i];
    __syncthreads();

    const int warp = blockIdx.x * WARPS_PER_BLOCK + (threadIdx.x >> 5);
    const int lane = threadIdx.x & 31;
    const int half = lane >> 4;                  // which 4-atom group of the batch
    const int sub  = lane & 15;                  // float4 column within the row
    const unsigned halfmask = 0xFFFFu << (half * 16);

    long long start = (long long)warp * atoms_per_warp;
    long long end   = start + atoms_per_warp;
    if (end > n_atoms) end = (long long)n_atoms;
    if (start >= end) return;                    // uniform per warp

    const long long n      = end - start;
    const long long nbatch = n >> 3;             // batches of 8 atoms

    int   cur_key = -1;
    float acc0 = 0.0f, acc1 = 0.0f;

    // Flush the current segment for this half-warp (call half-converged).
    auto flush = [&]() {
        float t = acc0 + acc1;
        t += __shfl_xor_sync(halfmask, t, 8);
        t += __shfl_xor_sync(halfmask, t, 4);
        t += __shfl_xor_sync(halfmask, t, 2);
        t += __shfl_xor_sync(halfmask, t, 1);
        if (sub == 0 && cur_key >= 0)
            atomicAdd(out + cur_key, t);
    };
    // Process one atom with boundary check (slow path / tail).
    auto proc1 = [&](int k, int s, float4 x) {
        if (k != cur_key) {
            flush();
            cur_key = k; acc0 = 0.0f; acc1 = 0.0f;
        }
        const float4 w = Wsh[s * D_VEC4 + sub];
        acc0 = fmaf(x.x, w.x, acc0);
        acc1 = fmaf(x.y, w.y, acc1);
        acc0 = fmaf(x.z, w.z, acc0);
        acc1 = fmaf(x.w, w.w, acc1);
    };

    // Hot-loop pointers (this half's first atom is start + half*4).
    const long long a0 = start + half * 4;
    const float4* xp = X4 + a0 * D_VEC4 + sub;
    const int*    kp = struct_idx + a0;
    const int*    sp = species + a0;

    for (long long b = 0; b < nbatch; ++b) {
        // Front-batched loads: 4 independent streaming float4s + vector keys.
        const float4 x0 = __ldcs(xp);
        const float4 x1 = __ldcs(xp + D_VEC4);
        const float4 x2 = __ldcs(xp + 2 * D_VEC4);
        const float4 x3 = __ldcs(xp + 3 * D_VEC4);
        const int4 kv = *reinterpret_cast<const int4*>(kp);
        const int4 sv = *reinterpret_cast<const int4*>(sp);
        xp += 8 * D_VEC4;   // 8 atoms forward (both halves)
        kp += 8;
        sp += 8;

        if (kv.x == cur_key && kv.w == cur_key) {
            // Whole batch inside the current segment (sorted keys): no
            // boundaries, straight FMAs.
            const float4 w0 = Wsh[sv.x * D_VEC4 + sub];
            const float4 w1 = Wsh[sv.y * D_VEC4 + sub];
            const float4 w2 = Wsh[sv.z * D_VEC4 + sub];
            const float4 w3 = Wsh[sv.w * D_VEC4 + sub];
            acc0 = fmaf(x0.x, w0.x, acc0); acc1 = fmaf(x0.y, w0.y, acc1);
            acc0 = fmaf(x0.z, w0.z, acc0); acc1 = fmaf(x0.w, w0.w, acc1);
            acc0 = fmaf(x1.x, w1.x, acc0); acc1 = fmaf(x1.y, w1.y, acc1);
            acc0 = fmaf(x1.z, w1.z, acc0); acc1 = fmaf(x1.w, w1.w, acc1);
            acc0 = fmaf(x2.x, w2.x, acc0); acc1 = fmaf(x2.y, w2.y, acc1);
            acc0 = fmaf(x2.z, w2.z, acc0); acc1 = fmaf(x2.w, w2.w, acc1);
            acc0 = fmaf(x3.x, w3.x, acc0); acc1 = fmaf(x3.y, w3.y, acc1);
            acc0 = fmaf(x3.z, w3.z, acc0); acc1 = fmaf(x3.w, w3.w, acc1);
        } else {
            proc1(kv.x, sv.x, x0);
            proc1(kv.y, sv.y, x1);
            proc1(kv.z, sv.z, x2);
            proc1(kv.w, sv.w, x3);
        }
    }

    // Tail (< 8 atoms, only in the last active warp): 2 atoms per step,
    // halves interleave; keys stay monotone per half.
    for (long long a = start + nbatch * 8 + half; a < end; a += 2) {
        const int k = struct_idx[a];
        const int s = species[a];
        const float4 x = __ldcs(&X4[a * D_VEC4 + sub]);
        proc1(k, s, x);
    }

    // Final flush (all lanes converged here).
    flush();
}

extern "C" void kernel_launch(void* const* d_in, const int* in_sizes, int n_in,
                              void* d_out, int out_size)
{
    // Input order: X, W, central_species, structural_indices, n_structures
    const float* X  = (const float*)d_in[0];
    const float* W  = (const float*)d_in[1];
    const int*   sp = (const int*)  d_in[2];
    const int*   si = (const int*)  d_in[3];
    float* out = (float*)d_out;

    const int n_atoms = in_sizes[2];

    cudaMemsetAsync(d_out, 0, (size_t)out_size * sizeof(float), 0);

    const int blocks = 1184;  // 148 SMs * 8 CTAs worth of warps in flight
    const int total_warps = blocks * WARPS_PER_BLOCK;
    // Round atoms_per_warp up to a multiple of 8 (keeps int4 loads aligned
    // and the main loop guard-free).
    int apw = (n_atoms + total_warps - 1) / total_warps;
    apw = (apw + 7) & ~7;

    atomistic_kernel<<<blocks, THREADS_PER_BLOCK>>>(
        (const float4*)X, W, sp, si, out, n_atoms, apw);
}

// round 5
// speedup vs baseline: 1.8097x; 1.0032x over previous
#include <cuda_runtime.h>
#include <cuda_bf16.h>

// Per-species linear (X[n,64] . W[species[n],64,1]) + segment_sum over sorted
// structural_indices -> out[n_structures].
// R4: 16-atom warp batches (each half-warp owns 8 contiguous atoms). Per lane:
// 8 front-batched independent __ldcs float4 X loads + 2 int4 key + 2 int4
// species loads -> MLP ~10 before first consume. 4 accumulators. Sorted-run
// fast path (whole 8-atom run in one segment -> 32 straight FMAs). Shuffle
// reduction + atomicAdd only at segment boundaries (~1/100 atoms).

#define WARPS_PER_BLOCK 8
#define THREADS_PER_BLOCK (WARPS_PER_BLOCK * 32)
#define N_SPECIES 8
#define D_VEC4 16   // 64 floats / 4

__global__ __launch_bounds__(THREADS_PER_BLOCK)
void atomistic_kernel(const float4* __restrict__ X4,
                      const float*  __restrict__ W,
                      const int*    __restrict__ species,
                      const int*    __restrict__ struct_idx,
                      float*        __restrict__ out,
                      int n_atoms,
                      int atoms_per_warp)   // multiple of 16
{
    __shared__ float4 Wsh[N_SPECIES * D_VEC4];
    for (int i = threadIdx.x; i < N_SPECIES * D_VEC4; i += blockDim.x)
        Wsh[i] = reinterpret_cast<const float4*>(W)[i];
    __syncthreads();

    const int warp = blockIdx.x * WARPS_PER_BLOCK + (threadIdx.x >> 5);
    const int lane = threadIdx.x & 31;
    const int half = lane >> 4;                  // which 8-atom group of the batch
    const int sub  = lane & 15;                  // float4 column within the row
    const unsigned halfmask = 0xFFFFu << (half * 16);

    long long start = (long long)warp * atoms_per_warp;
    long long end   = start + atoms_per_warp;
    if (end > n_atoms) end = (long long)n_atoms;
    if (start >= end) return;                    // uniform per warp

    const long long n      = end - start;
    const long long nbatch = n >> 4;             // batches of 16 atoms

    int   cur_key = -1;
    float acc0 = 0.0f, acc1 = 0.0f, acc2 = 0.0f, acc3 = 0.0f;

    // Flush the current segment for this half-warp (call half-converged).
    auto flush = [&]() {
        float t = (acc0 + acc1) + (acc2 + acc3);
        t += __shfl_xor_sync(halfmask, t, 8);
        t += __shfl_xor_sync(halfmask, t, 4);
        t += __shfl_xor_sync(halfmask, t, 2);
        t += __shfl_xor_sync(halfmask, t, 1);
        if (sub == 0 && cur_key >= 0)
            atomicAdd(out + cur_key, t);
    };
    // Process one atom with boundary check (slow path / tail).
    auto proc1 = [&](int k, int s, float4 x) {
        if (k != cur_key) {
            flush();
            cur_key = k; acc0 = acc1 = acc2 = acc3 = 0.0f;
        }
        const float4 w = Wsh[s * D_VEC4 + sub];
        acc0 = fmaf(x.x, w.x, acc0);
        acc1 = fmaf(x.y, w.y, acc1);
        acc2 = fmaf(x.z, w.z, acc2);
        acc3 = fmaf(x.w, w.w, acc3);
    };
    // One fully-loaded atom on the fast path.
    auto fma4 = [&](int s, const float4& x) {
        const float4 w = Wsh[s * D_VEC4 + sub];
        acc0 = fmaf(x.x, w.x, acc0);
        acc1 = fmaf(x.y, w.y, acc1);
        acc2 = fmaf(x.z, w.z, acc2);
        acc3 = fmaf(x.w, w.w, acc3);
    };

    // Hot-loop pointers (this half's first atom is start + half*8).
    const long long a0 = start + half * 8;
    const float4* xp = X4 + a0 * D_VEC4 + sub;
    const int*    kp = struct_idx + a0;
    const int*    sp = species + a0;

    for (long long b = 0; b < nbatch; ++b) {
        // Front-batched loads: 8 independent streaming float4s + vector keys.
        const float4 x0 = __ldcs(xp);
        const float4 x1 = __ldcs(xp + 1 * D_VEC4);
        const float4 x2 = __ldcs(xp + 2 * D_VEC4);
        const float4 x3 = __ldcs(xp + 3 * D_VEC4);
        const float4 x4 = __ldcs(xp + 4 * D_VEC4);
        const float4 x5 = __ldcs(xp + 5 * D_VEC4);
        const float4 x6 = __ldcs(xp + 6 * D_VEC4);
        const float4 x7 = __ldcs(xp + 7 * D_VEC4);
        const int4 kv0 = *reinterpret_cast<const int4*>(kp);
        const int4 kv1 = *reinterpret_cast<const int4*>(kp + 4);
        const int4 sv0 = *reinterpret_cast<const int4*>(sp);
        const int4 sv1 = *reinterpret_cast<const int4*>(sp + 4);
        xp += 16 * D_VEC4;   // 16 atoms forward (both halves)
        kp += 16;
        sp += 16;

        if (kv0.x == cur_key && kv1.w == cur_key) {
            // Sorted keys + first==last==cur -> all 8 atoms in current segment.
            fma4(sv0.x, x0); fma4(sv0.y, x1); fma4(sv0.z, x2); fma4(sv0.w, x3);
            fma4(sv1.x, x4); fma4(sv1.y, x5); fma4(sv1.z, x6); fma4(sv1.w, x7);
        } else {
            proc1(kv0.x, sv0.x, x0);
            proc1(kv0.y, sv0.y, x1);
            proc1(kv0.z, sv0.z, x2);
            proc1(kv0.w, sv0.w, x3);
            proc1(kv1.x, sv1.x, x4);
            proc1(kv1.y, sv1.y, x5);
            proc1(kv1.z, sv1.z, x6);
            proc1(kv1.w, sv1.w, x7);
        }
    }

    // Tail (< 16 atoms, only in the last active warp): 2 atoms per step,
    // halves interleave; keys stay monotone per half.
    for (long long a = start + nbatch * 16 + half; a < end; a += 2) {
        const int k = struct_idx[a];
        const int s = species[a];
        const float4 x = __ldcs(&X4[a * D_VEC4 + sub]);
        proc1(k, s, x);
    }

    // Final flush (all lanes converged here).
    flush();
}

extern "C" void kernel_launch(void* const* d_in, const int* in_sizes, int n_in,
                              void* d_out, int out_size)
{
    // Input order: X, W, central_species, structural_indices, n_structures
    const float* X  = (const float*)d_in[0];
    const float* W  = (const float*)d_in[1];
    const int*   sp = (const int*)  d_in[2];
    const int*   si = (const int*)  d_in[3];
    float* out = (float*)d_out;

    const int n_atoms = in_sizes[2];

    cudaMemsetAsync(d_out, 0, (size_t)out_size * sizeof(float), 0);

    const int blocks = 1184;
    const int total_warps = blocks * WARPS_PER_BLOCK;
    // Round atoms_per_warp up to a multiple of 16 (keeps int4 loads aligned
    // and the 16-atom main loop guard-free).
    int apw = (n_atoms + total_warps - 1) / total_warps;
    apw = (apw + 15) & ~15;

    atomistic_kernel<<<blocks, THREADS_PER_BLOCK>>>(
        (const float4*)X, W, sp, si, out, n_atoms, apw);
}